// round 1
// baseline (speedup 1.0000x reference)
#include <cuda_runtime.h>
#include <math.h>

#define Bq   4
#define Nn   192
#define Hh   128
#define NBt  3
#define ROWS (Bq*Nn)   // 768
#define TE   8

// ---- scratch (device globals; no allocs allowed) ----
__device__ float g_F[ROWS*Hh];
__device__ float g_preA[ROWS*Hh];
__device__ float g_preB[ROWS*Hh];
__device__ float g_agg[ROWS*Hh];
__device__ int   g_cnt[ROWS];
__device__ int   g_edgeJ[ROWS*Nn];          // global node index b*N+j
__device__ float g_edgeFeat[ROWS*Nn*10];    // rbf[6] + dir_feat[4]
__device__ float g_Wc[256*Hh];              // [RW ; DW] stacked (256 x 128)
__device__ float g_cvec[Hh];                // edge_b1 + rb2@W1c + db2@W1d

__device__ __forceinline__ float silu_f(float x) {
    return x / (1.0f + __expf(-x));
}

// feats = emb[node_indices]
__global__ void k_init(const int* __restrict__ idx, const float* __restrict__ emb) {
    int row = blockIdx.x, h = threadIdx.x;
    g_F[row*Hh + h] = emb[idx[row]*Hh + h];
}

// Build compacted edge list + block-invariant geometry features (rbf, tanh dir proj)
__global__ void k_edges(const float* __restrict__ pos, const int* __restrict__ adj,
                        const float* __restrict__ mask,
                        const float* __restrict__ dpw, const float* __restrict__ dpb) {
    int row = blockIdx.x;            // b*N + i
    int b = row / Nn, i = row % Nn;
    int j = threadIdx.x;             // 0..191
    __shared__ int cnt;
    if (j == 0) cnt = 0;
    __syncthreads();

    const float* pb = pos + (size_t)b*Nn*3;
    float xi = pb[i*3+0], yi = pb[i*3+1], zi = pb[i*3+2];
    float xj = pb[j*3+0], yj = pb[j*3+1], zj = pb[j*3+2];
    float dx = xi-xj, dy = yi-yj, dz = zi-zj;
    float dist = sqrtf(dx*dx + dy*dy + dz*dz);
    bool valid = (mask[row] > 0.f) && (mask[b*Nn + j] > 0.f) && (dist <= 5.0f)
                 && (adj[(size_t)b*Nn*Nn + (size_t)i*Nn + j] > 0) && (i != j);
    if (valid) {
        int e = atomicAdd(&cnt, 1);
        g_edgeJ[row*Nn + e] = b*Nn + j;
        float inv = 1.0f / (dist + 1e-8f);
        float ux = dx*inv, uy = dy*inv, uz = dz*inv;
        float* ft = &g_edgeFeat[(size_t)(row*Nn + e)*10];
        const float w = (5.0f/6.0f) + 1e-8f;
        #pragma unroll
        for (int r = 0; r < 6; r++) {
            float t = (dist - (float)r) / w;
            ft[r] = expf(-0.5f * t * t);
        }
        #pragma unroll
        for (int s = 0; s < 4; s++) {
            float v = ux*dpw[0*4+s] + uy*dpw[1*4+s] + uz*dpw[2*4+s] + dpb[s];
            ft[6+s] = tanhf(v);
        }
    }
    __syncthreads();
    if (j == 0) g_cnt[row] = cnt;
}

// Per-block weight folding: Wc = [rw2@W1c ; dw2@W1d], cvec = edge_b1 + rb2@W1c + db2@W1d
__global__ void k_fold(const float* __restrict__ rw2, const float* __restrict__ rb2,
                       const float* __restrict__ dw2, const float* __restrict__ db2,
                       const float* __restrict__ ew1, const float* __restrict__ eb1, int t) {
    int h = threadIdx.x;
    int kk = blockIdx.x;
    const float* W1c = ew1 + (size_t)t*4*Hh*Hh + 2*Hh*Hh;
    const float* W1d = ew1 + (size_t)t*4*Hh*Hh + 3*Hh*Hh;
    if (kk < 256) {
        const float* src = (kk < 128) ? (rw2 + (size_t)t*Hh*Hh + kk*Hh)
                                      : (dw2 + (size_t)t*Hh*Hh + (kk-128)*Hh);
        const float* W   = (kk < 128) ? W1c : W1d;
        __shared__ float srow[Hh];
        srow[h] = src[h];
        __syncthreads();
        float s = 0.f;
        #pragma unroll 4
        for (int m = 0; m < Hh; m++) s += srow[m] * W[m*Hh + h];
        g_Wc[kk*Hh + h] = s;
    } else {
        __shared__ float rb[Hh], db[Hh];
        rb[h] = rb2[t*Hh + h];
        db[h] = db2[t*Hh + h];
        __syncthreads();
        float s = eb1[t*Hh + h];
        #pragma unroll 4
        for (int m = 0; m < Hh; m++) s += rb[m]*W1c[m*Hh + h] + db[m]*W1d[m*Hh + h];
        g_cvec[h] = s;
    }
}

// Per-node precompute: preA = f@W1a, preB = f@W1b
__global__ void k_pre(const float* __restrict__ ew1, int t) {
    int row = blockIdx.x, h = threadIdx.x;
    __shared__ float f[Hh];
    f[h] = g_F[row*Hh + h];
    __syncthreads();
    const float* W1a = ew1 + (size_t)t*4*Hh*Hh;
    const float* W1b = W1a + Hh*Hh;
    float a = 0.f, bv = 0.f;
    #pragma unroll 4
    for (int k = 0; k < Hh; k++) {
        float fk = f[k];
        a  += fk * W1a[k*Hh + h];
        bv += fk * W1b[k*Hh + h];
    }
    g_preA[row*Hh + h] = a;
    g_preB[row*Hh + h] = bv;
}

// Edge MLP + aggregation: one CTA per (b,i) row, TE edges register-blocked
__global__ void k_edge_mlp(const float* __restrict__ rw1, const float* __restrict__ rb1,
                           const float* __restrict__ dw1, const float* __restrict__ db1, int t) {
    int row = blockIdx.x, h = threadIdx.x;
    int nE = g_cnt[row];
    const float* RW1 = rw1 + t*6*Hh;
    const float* DW1 = dw1 + t*4*Hh;
    float rb1h = rb1[t*Hh + h], db1h = db1[t*Hh + h];
    float base = g_preA[row*Hh + h] + g_cvec[h];
    float acc = 0.f;
    __shared__ float sh[256*TE];   // hcomb laid out [k][e] for vector LDS on read

    for (int e0 = 0; e0 < nE; e0 += TE) {
        int ne = min(TE, nE - e0);
        __syncthreads();
        #pragma unroll
        for (int e = 0; e < TE; e++) {
            if (e < ne) {
                const float* ft = &g_edgeFeat[(size_t)(row*Nn + e0 + e)*10];
                float a = rb1h;
                #pragma unroll
                for (int r = 0; r < 6; r++) a += ft[r] * RW1[r*Hh + h];
                sh[h*TE + e] = silu_f(a);
                float bb = db1h;
                #pragma unroll
                for (int r = 0; r < 4; r++) bb += ft[6+r] * DW1[r*Hh + h];
                sh[(128 + h)*TE + e] = silu_f(bb);
            } else {
                sh[h*TE + e] = 0.f;
                sh[(128 + h)*TE + e] = 0.f;
            }
        }
        __syncthreads();
        float g[TE];
        #pragma unroll
        for (int e = 0; e < TE; e++)
            g[e] = (e < ne) ? (base + g_preB[g_edgeJ[row*Nn + e0 + e]*Hh + h]) : 0.f;
        #pragma unroll 2
        for (int k = 0; k < 256; k++) {
            float w = g_Wc[k*Hh + h];
            #pragma unroll
            for (int e = 0; e < TE; e++) g[e] += sh[k*TE + e] * w;
        }
        #pragma unroll
        for (int e = 0; e < TE; e++)
            if (e < ne) acc += silu_f(g[e]);
    }
    g_agg[row*Hh + h] = acc;
}

// aggOut = agg@ew2 + deg*eb2; update = MLP([f,aggOut]); f += update
__global__ void k_node(const float* __restrict__ ew2, const float* __restrict__ eb2,
                       const float* __restrict__ nw1, const float* __restrict__ nb1,
                       const float* __restrict__ nw2, const float* __restrict__ nb2, int t) {
    int row = blockIdx.x, h = threadIdx.x;
    __shared__ float x[256];
    __shared__ float agg_s[Hh];
    __shared__ float u[Hh];
    float fh = g_F[row*Hh + h];
    x[h] = fh;
    agg_s[h] = g_agg[row*Hh + h];
    __syncthreads();
    const float* EW2 = ew2 + (size_t)t*Hh*Hh;
    float deg = (float)g_cnt[row];
    float s = deg * eb2[t*Hh + h];
    #pragma unroll 4
    for (int k = 0; k < Hh; k++) s += agg_s[k] * EW2[k*Hh + h];
    x[128 + h] = s;
    __syncthreads();
    const float* NW1 = nw1 + (size_t)t*256*Hh;
    float uacc = nb1[t*Hh + h];
    #pragma unroll 4
    for (int k = 0; k < 256; k++) uacc += x[k] * NW1[k*Hh + h];
    u[h] = silu_f(uacc);
    __syncthreads();
    const float* NW2 = nw2 + (size_t)t*Hh*Hh;
    float upd = nb2[t*Hh + h];
    #pragma unroll 4
    for (int k = 0; k < Hh; k++) upd += u[k] * NW2[k*Hh + h];
    g_F[row*Hh + h] = fh + upd;
}

// Output head: per_atom = MLP(f) * mask; energy[b] = sum_i per_atom
__global__ void k_out(const float* __restrict__ ow1, const float* __restrict__ ob1,
                      const float* __restrict__ ow2, const float* __restrict__ ob2,
                      const float* __restrict__ mask, float* __restrict__ out) {
    int row = blockIdx.x, h = threadIdx.x;
    __shared__ float f[Hh];
    __shared__ float red[4];
    f[h] = g_F[row*Hh + h];
    __syncthreads();
    float uacc = ob1[h];
    #pragma unroll 4
    for (int k = 0; k < Hh; k++) uacc += f[k] * ow1[k*Hh + h];
    float val = silu_f(uacc) * ow2[h];
    #pragma unroll
    for (int off = 16; off > 0; off >>= 1) val += __shfl_down_sync(0xffffffffu, val, off);
    if ((h & 31) == 0) red[h >> 5] = val;
    __syncthreads();
    if (h == 0) {
        float v = red[0] + red[1] + red[2] + red[3] + ob2[0];
        v *= mask[row];
        atomicAdd(&out[row / Nn], v);
    }
}

__global__ void k_zero(float* out) {
    if (threadIdx.x < Bq) out[threadIdx.x] = 0.f;
}

extern "C" void kernel_launch(void* const* d_in, const int* in_sizes, int n_in,
                              void* d_out, int out_size) {
    const int*   node_indices = (const int*)  d_in[0];
    const float* positions    = (const float*)d_in[1];
    const int*   adjacency    = (const int*)  d_in[2];
    const float* mask         = (const float*)d_in[3];
    const float* emb          = (const float*)d_in[4];
    const float* dpw          = (const float*)d_in[5];
    const float* dpb          = (const float*)d_in[6];
    const float* rbf_w1 = (const float*)d_in[7];
    const float* rbf_b1 = (const float*)d_in[8];
    const float* rbf_w2 = (const float*)d_in[9];
    const float* rbf_b2 = (const float*)d_in[10];
    const float* dir_w1 = (const float*)d_in[11];
    const float* dir_b1 = (const float*)d_in[12];
    const float* dir_w2 = (const float*)d_in[13];
    const float* dir_b2 = (const float*)d_in[14];
    const float* edge_w1 = (const float*)d_in[15];
    const float* edge_b1 = (const float*)d_in[16];
    const float* edge_w2 = (const float*)d_in[17];
    const float* edge_b2 = (const float*)d_in[18];
    const float* node_w1 = (const float*)d_in[19];
    const float* node_b1 = (const float*)d_in[20];
    const float* node_w2 = (const float*)d_in[21];
    const float* node_b2 = (const float*)d_in[22];
    const float* ow1 = (const float*)d_in[23];
    const float* ob1 = (const float*)d_in[24];
    const float* ow2 = (const float*)d_in[25];
    const float* ob2 = (const float*)d_in[26];
    float* out = (float*)d_out;

    k_zero<<<1, 32>>>(out);
    k_init<<<ROWS, Hh>>>(node_indices, emb);
    k_edges<<<ROWS, Nn>>>(positions, adjacency, mask, dpw, dpb);
    for (int t = 0; t < NBt; t++) {
        k_fold<<<257, Hh>>>(rbf_w2, rbf_b2, dir_w2, dir_b2, edge_w1, edge_b1, t);
        k_pre<<<ROWS, Hh>>>(edge_w1, t);
        k_edge_mlp<<<ROWS, Hh>>>(rbf_w1, rbf_b1, dir_w1, dir_b1, t);
        k_node<<<ROWS, Hh>>>(edge_w2, edge_b2, node_w1, node_b1, node_w2, node_b2, t);
    }
    k_out<<<ROWS, Hh>>>(ow1, ob1, ow2, ob2, mask, out);
}

// round 2
// speedup vs baseline: 2.2577x; 2.2577x over previous
#include <cuda_runtime.h>
#include <math.h>

#define Bq   4
#define Nn   192
#define Hh   128
#define NBt  3
#define ROWS (Bq*Nn)       // 768
#define EMAX (ROWS*Nn)     // worst-case edges
#define TE   8
#define GRID_E 1184

// ---- scratch (device globals; no allocs allowed) ----
__device__ float g_F[ROWS*Hh];
__device__ float g_preA[ROWS*Hh];
__device__ float g_preB[ROWS*Hh];
__device__ float g_agg[ROWS*Hh];
__device__ int   g_cnt[ROWS];
__device__ int   g_nE;
__device__ int   g_eI[EMAX];
__device__ int   g_eJ[EMAX];
__device__ float g_feat[(size_t)EMAX*10];   // rbf[6] + dir_feat[4]
__device__ float g_Wc[NBt*256*Hh];          // per-block folded [RW ; DW] (256 x 128)
__device__ float g_cvec[NBt*Hh];            // per-block edge_b1 + rb2@W1c + db2@W1d

__device__ __forceinline__ float silu_f(float x) {
    return x / (1.0f + __expf(-x));
}

__device__ __forceinline__ unsigned long long fma2(unsigned long long a,
                                                   unsigned long long b,
                                                   unsigned long long c) {
    unsigned long long d;
    asm("fma.rn.f32x2 %0, %1, %2, %3;" : "=l"(d) : "l"(a), "l"(b), "l"(c));
    return d;
}
__device__ __forceinline__ unsigned long long pack2(float lo, float hi) {
    unsigned long long d;
    asm("mov.b64 %0, {%1, %2};" : "=l"(d) : "f"(lo), "f"(hi));
    return d;
}
__device__ __forceinline__ void unpack2(unsigned long long v, float& lo, float& hi) {
    asm("mov.b64 {%0, %1}, %2;" : "=f"(lo), "=f"(hi) : "l"(v));
}

// feats = emb[node_indices]; preA/preB for block 0; zero agg/out/edge-counter
__global__ void k_init(const int* __restrict__ idx, const float* __restrict__ emb,
                       const float* __restrict__ ew1, float* __restrict__ out) {
    int row = blockIdx.x, h = threadIdx.x;
    __shared__ float f[Hh];
    float v = emb[idx[row]*Hh + h];
    g_F[row*Hh + h] = v;
    f[h] = v;
    if (row == 0 && h < Bq) out[h] = 0.f;
    if (row == 0 && h == 0) g_nE = 0;
    __syncthreads();
    const float* W1a = ew1;            // block 0
    const float* W1b = ew1 + Hh*Hh;
    float a = 0.f, bv = 0.f;
    #pragma unroll 4
    for (int k = 0; k < Hh; k++) {
        float fk = f[k];
        a  += fk * W1a[k*Hh + h];
        bv += fk * W1b[k*Hh + h];
    }
    g_preA[row*Hh + h] = a;
    g_preB[row*Hh + h] = bv;
    g_agg[row*Hh + h] = 0.f;
}

// Build flat edge list + block-invariant geometry features
__global__ void k_edges(const float* __restrict__ pos, const int* __restrict__ adj,
                        const float* __restrict__ mask,
                        const float* __restrict__ dpw, const float* __restrict__ dpb) {
    int row = blockIdx.x;            // b*N + i
    int b = row / Nn, i = row % Nn;
    int j = threadIdx.x;             // 0..191
    __shared__ int s_cnt, s_base;
    if (j == 0) s_cnt = 0;
    __syncthreads();

    const float* pb = pos + (size_t)b*Nn*3;
    float xi = pb[i*3+0], yi = pb[i*3+1], zi = pb[i*3+2];
    float xj = pb[j*3+0], yj = pb[j*3+1], zj = pb[j*3+2];
    float dx = xi-xj, dy = yi-yj, dz = zi-zj;
    float dist = sqrtf(dx*dx + dy*dy + dz*dz);
    bool valid = (mask[row] > 0.f) && (mask[b*Nn + j] > 0.f) && (dist <= 5.0f)
                 && (adj[(size_t)b*Nn*Nn + (size_t)i*Nn + j] > 0) && (i != j);
    int el = -1;
    float ft[10];
    if (valid) {
        el = atomicAdd(&s_cnt, 1);
        float inv = 1.0f / (dist + 1e-8f);
        float ux = dx*inv, uy = dy*inv, uz = dz*inv;
        const float w = (5.0f/6.0f) + 1e-8f;
        #pragma unroll
        for (int r = 0; r < 6; r++) {
            float t = (dist - (float)r) / w;
            ft[r] = expf(-0.5f * t * t);
        }
        #pragma unroll
        for (int s = 0; s < 4; s++) {
            float vv = ux*dpw[0*4+s] + uy*dpw[1*4+s] + uz*dpw[2*4+s] + dpb[s];
            ft[6+s] = tanhf(vv);
        }
    }
    __syncthreads();
    if (j == 0) {
        g_cnt[row] = s_cnt;
        s_base = atomicAdd(&g_nE, s_cnt);
    }
    __syncthreads();
    if (valid) {
        int e = s_base + el;
        g_eI[e] = row;
        g_eJ[e] = b*Nn + j;
        float* fo = &g_feat[(size_t)e*10];
        #pragma unroll
        for (int r = 0; r < 10; r++) fo[r] = ft[r];
    }
}

// All 3 blocks' weight folding in one launch
__global__ void k_fold(const float* __restrict__ rw2, const float* __restrict__ rb2,
                       const float* __restrict__ dw2, const float* __restrict__ db2,
                       const float* __restrict__ ew1, const float* __restrict__ eb1) {
    int h = threadIdx.x;
    int t  = blockIdx.x / 257;
    int kk = blockIdx.x % 257;
    const float* W1c = ew1 + (size_t)t*4*Hh*Hh + 2*Hh*Hh;
    const float* W1d = ew1 + (size_t)t*4*Hh*Hh + 3*Hh*Hh;
    if (kk < 256) {
        const float* src = (kk < 128) ? (rw2 + (size_t)t*Hh*Hh + kk*Hh)
                                      : (dw2 + (size_t)t*Hh*Hh + (kk-128)*Hh);
        const float* W   = (kk < 128) ? W1c : W1d;
        __shared__ float srow[Hh];
        srow[h] = src[h];
        __syncthreads();
        float s = 0.f;
        #pragma unroll 4
        for (int m = 0; m < Hh; m++) s += srow[m] * W[m*Hh + h];
        g_Wc[(t*256 + kk)*Hh + h] = s;
    } else {
        __shared__ float rb[Hh], db[Hh];
        rb[h] = rb2[t*Hh + h];
        db[h] = db2[t*Hh + h];
        __syncthreads();
        float s = eb1[t*Hh + h];
        #pragma unroll 4
        for (int m = 0; m < Hh; m++) s += rb[m]*W1c[m*Hh + h] + db[m]*W1d[m*Hh + h];
        g_cvec[t*Hh + h] = s;
    }
}

// Balanced flat edge MLP + atomic aggregation. Grid-stride over 8-edge tiles.
__global__ void k_edge_mlp(const float* __restrict__ rw1, const float* __restrict__ rb1,
                           const float* __restrict__ dw1, const float* __restrict__ db1, int t) {
    int h = threadIdx.x;
    const float* RW1 = rw1 + t*6*Hh;
    const float* DW1 = dw1 + t*4*Hh;
    const float* Wc  = g_Wc + (size_t)t*256*Hh;
    float rb1h = rb1[t*Hh + h], db1h = db1[t*Hh + h];
    float cv = g_cvec[t*Hh + h];
    float rw[6], dw[4];
    #pragma unroll
    for (int r = 0; r < 6; r++) rw[r] = RW1[r*Hh + h];
    #pragma unroll
    for (int r = 0; r < 4; r++) dw[r] = DW1[r*Hh + h];

    __shared__ float sh[256*TE];      // [k][e], e contiguous (16B-aligned pairs)
    __shared__ int s_eI[TE], s_eJ[TE];

    int nE = g_nE;
    int nT = (nE + TE - 1) / TE;

    for (int tile = blockIdx.x; tile < nT; tile += gridDim.x) {
        int e0 = tile * TE;
        int ne = min(TE, nE - e0);
        __syncthreads();   // sh reuse fence
        if (h < TE) {
            int idx = (h < ne) ? (e0 + h) : e0;
            s_eI[h] = g_eI[idx];
            s_eJ[h] = g_eJ[idx];
        }
        #pragma unroll
        for (int e = 0; e < TE; e++) {
            if (e < ne) {
                const float* ft = &g_feat[(size_t)(e0 + e)*10];
                float a = rb1h;
                #pragma unroll
                for (int r = 0; r < 6; r++) a += ft[r] * rw[r];
                float bb = db1h;
                #pragma unroll
                for (int r = 0; r < 4; r++) bb += ft[6+r] * dw[r];
                sh[h*TE + e]        = silu_f(a);
                sh[(128+h)*TE + e]  = silu_f(bb);
            } else {
                sh[h*TE + e]       = 0.f;
                sh[(128+h)*TE + e] = 0.f;
            }
        }
        __syncthreads();

        // base per edge = preA[i] + preB[j] + cvec
        float basef[TE];
        #pragma unroll
        for (int e = 0; e < TE; e++)
            basef[e] = g_preA[s_eI[e]*Hh + h] + g_preB[s_eJ[e]*Hh + h] + cv;
        unsigned long long g[4];
        #pragma unroll
        for (int p = 0; p < 4; p++) g[p] = pack2(basef[2*p], basef[2*p+1]);

        #pragma unroll 4
        for (int k = 0; k < 256; k++) {
            float w = __ldg(&Wc[k*Hh + h]);
            unsigned long long ww = pack2(w, w);
            const ulonglong2 s01 = *(const ulonglong2*)&sh[k*TE];
            const ulonglong2 s23 = *(const ulonglong2*)&sh[k*TE + 4];
            g[0] = fma2(s01.x, ww, g[0]);
            g[1] = fma2(s01.y, ww, g[1]);
            g[2] = fma2(s23.x, ww, g[2]);
            g[3] = fma2(s23.y, ww, g[3]);
        }

        #pragma unroll
        for (int p = 0; p < 4; p++) {
            float lo, hi;
            unpack2(g[p], lo, hi);
            int e = 2*p;
            if (e < ne)     atomicAdd(&g_agg[s_eI[e]*Hh + h],   silu_f(lo));
            if (e + 1 < ne) atomicAdd(&g_agg[s_eI[e+1]*Hh + h], silu_f(hi));
        }
    }
}

// aggOut = agg@ew2 + deg*eb2; update MLP; f += update; then preA/preB for t+1 + zero agg
__global__ void k_node(const float* __restrict__ ew2, const float* __restrict__ eb2,
                       const float* __restrict__ nw1, const float* __restrict__ nb1,
                       const float* __restrict__ nw2, const float* __restrict__ nb2,
                       const float* __restrict__ ew1, int t) {
    int row = blockIdx.x, h = threadIdx.x;
    __shared__ float x[256];
    __shared__ float agg_s[Hh];
    __shared__ float u[Hh];
    float fh = g_F[row*Hh + h];
    x[h] = fh;
    agg_s[h] = g_agg[row*Hh + h];
    __syncthreads();
    const float* EW2 = ew2 + (size_t)t*Hh*Hh;
    float deg = (float)g_cnt[row];
    float s = deg * eb2[t*Hh + h];
    #pragma unroll 4
    for (int k = 0; k < Hh; k++) s += agg_s[k] * EW2[k*Hh + h];
    x[128 + h] = s;
    __syncthreads();
    const float* NW1 = nw1 + (size_t)t*256*Hh;
    float uacc = nb1[t*Hh + h];
    #pragma unroll 4
    for (int k = 0; k < 256; k++) uacc += x[k] * NW1[k*Hh + h];
    u[h] = silu_f(uacc);
    __syncthreads();
    const float* NW2 = nw2 + (size_t)t*Hh*Hh;
    float upd = nb2[t*Hh + h];
    #pragma unroll 4
    for (int k = 0; k < Hh; k++) upd += u[k] * NW2[k*Hh + h];
    float newf = fh + upd;
    g_F[row*Hh + h] = newf;

    if (t + 1 < NBt) {
        x[h] = newf;              // x free: last read was before the u-sync
        __syncthreads();
        const float* W1a = ew1 + (size_t)(t+1)*4*Hh*Hh;
        const float* W1b = W1a + Hh*Hh;
        float a = 0.f, bv = 0.f;
        #pragma unroll 4
        for (int k = 0; k < Hh; k++) {
            float fk = x[k];
            a  += fk * W1a[k*Hh + h];
            bv += fk * W1b[k*Hh + h];
        }
        g_preA[row*Hh + h] = a;
        g_preB[row*Hh + h] = bv;
        g_agg[row*Hh + h] = 0.f;
    }
}

// Output head: per_atom = MLP(f) * mask; energy[b] = sum_i per_atom
__global__ void k_out(const float* __restrict__ ow1, const float* __restrict__ ob1,
                      const float* __restrict__ ow2, const float* __restrict__ ob2,
                      const float* __restrict__ mask, float* __restrict__ out) {
    int row = blockIdx.x, h = threadIdx.x;
    __shared__ float f[Hh];
    __shared__ float red[4];
    f[h] = g_F[row*Hh + h];
    __syncthreads();
    float uacc = ob1[h];
    #pragma unroll 4
    for (int k = 0; k < Hh; k++) uacc += f[k] * ow1[k*Hh + h];
    float val = silu_f(uacc) * ow2[h];
    #pragma unroll
    for (int off = 16; off > 0; off >>= 1) val += __shfl_down_sync(0xffffffffu, val, off);
    if ((h & 31) == 0) red[h >> 5] = val;
    __syncthreads();
    if (h == 0) {
        float v = red[0] + red[1] + red[2] + red[3] + ob2[0];
        v *= mask[row];
        atomicAdd(&out[row / Nn], v);
    }
}

extern "C" void kernel_launch(void* const* d_in, const int* in_sizes, int n_in,
                              void* d_out, int out_size) {
    const int*   node_indices = (const int*)  d_in[0];
    const float* positions    = (const float*)d_in[1];
    const int*   adjacency    = (const int*)  d_in[2];
    const float* mask         = (const float*)d_in[3];
    const float* emb          = (const float*)d_in[4];
    const float* dpw          = (const float*)d_in[5];
    const float* dpb          = (const float*)d_in[6];
    const float* rbf_w1 = (const float*)d_in[7];
    const float* rbf_b1 = (const float*)d_in[8];
    const float* rbf_w2 = (const float*)d_in[9];
    const float* rbf_b2 = (const float*)d_in[10];
    const float* dir_w1 = (const float*)d_in[11];
    const float* dir_b1 = (const float*)d_in[12];
    const float* dir_w2 = (const float*)d_in[13];
    const float* dir_b2 = (const float*)d_in[14];
    const float* edge_w1 = (const float*)d_in[15];
    const float* edge_b1 = (const float*)d_in[16];
    const float* edge_w2 = (const float*)d_in[17];
    const float* edge_b2 = (const float*)d_in[18];
    const float* node_w1 = (const float*)d_in[19];
    const float* node_b1 = (const float*)d_in[20];
    const float* node_w2 = (const float*)d_in[21];
    const float* node_b2 = (const float*)d_in[22];
    const float* ow1 = (const float*)d_in[23];
    const float* ob1 = (const float*)d_in[24];
    const float* ow2 = (const float*)d_in[25];
    const float* ob2 = (const float*)d_in[26];
    float* out = (float*)d_out;

    k_init<<<ROWS, Hh>>>(node_indices, emb, edge_w1, out);
    k_edges<<<ROWS, Nn>>>(positions, adjacency, mask, dpw, dpb);
    k_fold<<<3*257, Hh>>>(rbf_w2, rbf_b2, dir_w2, dir_b2, edge_w1, edge_b1);
    for (int t = 0; t < NBt; t++) {
        k_edge_mlp<<<GRID_E, Hh>>>(rbf_w1, rbf_b1, dir_w1, dir_b1, t);
        k_node<<<ROWS, Hh>>>(edge_w2, edge_b2, node_w1, node_b1, node_w2, node_b2, edge_w1, t);
    }
    k_out<<<ROWS, Hh>>>(ow1, ob1, ow2, ob2, mask, out);
}

// round 3
// speedup vs baseline: 2.2857x; 1.0124x over previous
#include <cuda_runtime.h>
#include <math.h>

#define Bq   4
#define Nn   192
#define Hh   128
#define NBt  3
#define ROWS (Bq*Nn)       // 768
#define EMAX (ROWS*Nn)     // worst-case edges
#define TE   16            // edges per tile
#define FST  12            // padded feature stride (floats)
#define SHS  20            // sh row stride in floats (80B, 16B-aligned, 4-way conflict)
#define GRID_E 1184

typedef unsigned long long ull;

// ---- scratch (device globals; no allocs allowed) ----
__device__ float g_F[ROWS*Hh];
__device__ float g_preA[ROWS*Hh];
__device__ float g_preB[ROWS*Hh];
__device__ float g_agg[ROWS*Hh];
__device__ int   g_cnt[ROWS];
__device__ int   g_nE;
__device__ int   g_eI[EMAX];
__device__ int   g_eJ[EMAX];
__device__ float g_feat[(size_t)EMAX*FST];  // rbf[6] + dir[4] + pad[2]
__device__ float g_Wc[NBt*256*Hh];          // folded [RW ; DW] per block
__device__ float g_cvec[NBt*Hh];            // edge_b1 + rb2@W1c + db2@W1d

__device__ __forceinline__ float silu_f(float x) {
    return x / (1.0f + __expf(-x));
}
__device__ __forceinline__ ull fma2(ull a, ull b, ull c) {
    ull d;
    asm("fma.rn.f32x2 %0, %1, %2, %3;" : "=l"(d) : "l"(a), "l"(b), "l"(c));
    return d;
}
__device__ __forceinline__ ull pack2(float lo, float hi) {
    ull d;
    asm("mov.b64 %0, {%1, %2};" : "=l"(d) : "f"(lo), "f"(hi));
    return d;
}
__device__ __forceinline__ void unpack2(ull v, float& lo, float& hi) {
    asm("mov.b64 {%0, %1}, %2;" : "=f"(lo), "=f"(hi) : "l"(v));
}

// feats = emb[idx]; preA/preB for block 0; zero agg/out/counter
__global__ void k_init(const int* __restrict__ idx, const float* __restrict__ emb,
                       const float* __restrict__ ew1, float* __restrict__ out) {
    int row = blockIdx.x, h = threadIdx.x;
    __shared__ float f[Hh];
    float v = emb[idx[row]*Hh + h];
    g_F[row*Hh + h] = v;
    f[h] = v;
    if (row == 0 && h < Bq) out[h] = 0.f;
    if (row == 0 && h == 0) g_nE = 0;
    __syncthreads();
    const float* W1a = ew1;
    const float* W1b = ew1 + Hh*Hh;
    float a = 0.f, bv = 0.f;
    #pragma unroll 4
    for (int k = 0; k < Hh; k++) {
        float fk = f[k];
        a  += fk * W1a[k*Hh + h];
        bv += fk * W1b[k*Hh + h];
    }
    g_preA[row*Hh + h] = a;
    g_preB[row*Hh + h] = bv;
    g_agg[row*Hh + h] = 0.f;
}

// Flat edge list + block-invariant geometry (rbf, tanh dir proj)
__global__ void k_edges(const float* __restrict__ pos, const int* __restrict__ adj,
                        const float* __restrict__ mask,
                        const float* __restrict__ dpw, const float* __restrict__ dpb) {
    int row = blockIdx.x;
    int b = row / Nn, i = row % Nn;
    int j = threadIdx.x;
    __shared__ int s_cnt, s_base;
    if (j == 0) s_cnt = 0;
    __syncthreads();

    const float* pb = pos + (size_t)b*Nn*3;
    float xi = pb[i*3+0], yi = pb[i*3+1], zi = pb[i*3+2];
    float xj = pb[j*3+0], yj = pb[j*3+1], zj = pb[j*3+2];
    float dx = xi-xj, dy = yi-yj, dz = zi-zj;
    float dist = sqrtf(dx*dx + dy*dy + dz*dz);
    bool valid = (mask[row] > 0.f) && (mask[b*Nn + j] > 0.f) && (dist <= 5.0f)
                 && (adj[(size_t)b*Nn*Nn + (size_t)i*Nn + j] > 0) && (i != j);
    int el = -1;
    float ft[10];
    if (valid) {
        el = atomicAdd(&s_cnt, 1);
        float inv = 1.0f / (dist + 1e-8f);
        float ux = dx*inv, uy = dy*inv, uz = dz*inv;
        const float w = (5.0f/6.0f) + 1e-8f;
        #pragma unroll
        for (int r = 0; r < 6; r++) {
            float t = (dist - (float)r) / w;
            ft[r] = expf(-0.5f * t * t);
        }
        #pragma unroll
        for (int s = 0; s < 4; s++) {
            float vv = ux*dpw[0*4+s] + uy*dpw[1*4+s] + uz*dpw[2*4+s] + dpb[s];
            ft[6+s] = tanhf(vv);
        }
    }
    __syncthreads();
    if (j == 0) {
        g_cnt[row] = s_cnt;
        s_base = atomicAdd(&g_nE, s_cnt);
    }
    __syncthreads();
    if (valid) {
        int e = s_base + el;
        g_eI[e] = row;
        g_eJ[e] = b*Nn + j;
        float4* fo = (float4*)&g_feat[(size_t)e*FST];
        fo[0] = make_float4(ft[0], ft[1], ft[2], ft[3]);
        fo[1] = make_float4(ft[4], ft[5], ft[6], ft[7]);
        fo[2] = make_float4(ft[8], ft[9], 0.f, 0.f);
    }
}

// All 3 blocks' weight folding
__global__ void k_fold(const float* __restrict__ rw2, const float* __restrict__ rb2,
                       const float* __restrict__ dw2, const float* __restrict__ db2,
                       const float* __restrict__ ew1, const float* __restrict__ eb1) {
    int h = threadIdx.x;
    int t  = blockIdx.x / 257;
    int kk = blockIdx.x % 257;
    const float* W1c = ew1 + (size_t)t*4*Hh*Hh + 2*Hh*Hh;
    const float* W1d = ew1 + (size_t)t*4*Hh*Hh + 3*Hh*Hh;
    if (kk < 256) {
        const float* src = (kk < 128) ? (rw2 + (size_t)t*Hh*Hh + kk*Hh)
                                      : (dw2 + (size_t)t*Hh*Hh + (kk-128)*Hh);
        const float* W   = (kk < 128) ? W1c : W1d;
        __shared__ float srow[Hh];
        srow[h] = src[h];
        __syncthreads();
        float s = 0.f;
        #pragma unroll 4
        for (int m = 0; m < Hh; m++) s += srow[m] * W[m*Hh + h];
        g_Wc[(t*256 + kk)*Hh + h] = s;
    } else {
        __shared__ float rb[Hh], db[Hh];
        rb[h] = rb2[t*Hh + h];
        db[h] = db2[t*Hh + h];
        __syncthreads();
        float s = eb1[t*Hh + h];
        #pragma unroll 4
        for (int m = 0; m < Hh; m++) s += rb[m]*W1c[m*Hh + h] + db[m]*W1d[m*Hh + h];
        g_cvec[t*Hh + h] = s;
    }
}

// Edge MLP + aggregation. 16-edge tiles, WH=2 h-blocking, run-compressed atomics.
__global__ void __launch_bounds__(Hh, 8)
k_edge_mlp(const float* __restrict__ rw1, const float* __restrict__ rb1,
           const float* __restrict__ dw1, const float* __restrict__ db1, int t) {
    int tid = threadIdx.x;
    const float* RW1 = rw1 + t*6*Hh;
    const float* DW1 = dw1 + t*4*Hh;
    const float2* Wc2 = (const float2*)(g_Wc + (size_t)t*256*Hh);
    float rb1h = rb1[t*Hh + tid], db1h = db1[t*Hh + tid];

    float rw[6], dwv[4];
    #pragma unroll
    for (int r = 0; r < 6; r++) rw[r] = RW1[r*Hh + tid];
    #pragma unroll
    for (int r = 0; r < 4; r++) dwv[r] = DW1[r*Hh + tid];

    int hw    = tid & 63;      // h-pair index: h = 2*hw, 2*hw+1
    int ehalf = tid >> 6;      // 0: edges 0-7, 1: edges 8-15
    int eoff  = ehalf * 8;
    float2 cv = ((const float2*)g_cvec)[t*64 + hw];

    __shared__ float sh[256*SHS];
    __shared__ int s_eI[TE], s_eJ[TE];

    int nE = g_nE;
    int nT = (nE + TE - 1) / TE;

    for (int tile = blockIdx.x; tile < nT; tile += gridDim.x) {
        int e0 = tile * TE;
        int ne = min(TE, nE - e0);
        __syncthreads();
        if (tid < TE) {
            int idx = (tid < ne) ? (e0 + tid) : e0;
            s_eI[tid] = g_eI[idx];
            s_eJ[tid] = g_eJ[idx];
        }
        // hidden build: thread computes k=tid (rbf) and k=tid+128 (dir), all 16 edges
        #pragma unroll
        for (int half = 0; half < 2; half++) {
            float va[8], vb[8];
            #pragma unroll
            for (int e = 0; e < 8; e++) {
                int ge = half*8 + e;
                if (ge < ne) {
                    const float4* fp = (const float4*)&g_feat[(size_t)(e0+ge)*FST];
                    float4 fa = fp[0], fb4 = fp[1], fc = fp[2];
                    float a = rb1h + fa.x*rw[0] + fa.y*rw[1] + fa.z*rw[2]
                                   + fa.w*rw[3] + fb4.x*rw[4] + fb4.y*rw[5];
                    float bb = db1h + fb4.z*dwv[0] + fb4.w*dwv[1]
                                    + fc.x*dwv[2] + fc.y*dwv[3];
                    va[e] = silu_f(a);
                    vb[e] = silu_f(bb);
                } else { va[e] = 0.f; vb[e] = 0.f; }
            }
            float4* rowA = (float4*)&sh[tid*SHS + half*8];
            float4* rowB = (float4*)&sh[(128+tid)*SHS + half*8];
            rowA[0] = make_float4(va[0], va[1], va[2], va[3]);
            rowA[1] = make_float4(va[4], va[5], va[6], va[7]);
            rowB[0] = make_float4(vb[0], vb[1], vb[2], vb[3]);
            rowB[1] = make_float4(vb[4], vb[5], vb[6], vb[7]);
        }
        __syncthreads();

        // base = preA[i] + preB[j] + cvec for this thread's h-pair, 8 edges
        ull gA[4], gB[4];
        #pragma unroll
        for (int p = 0; p < 4; p++) {
            float2 a0 = ((const float2*)g_preA)[s_eI[eoff+2*p]*64 + hw];
            float2 b0 = ((const float2*)g_preB)[s_eJ[eoff+2*p]*64 + hw];
            float2 a1 = ((const float2*)g_preA)[s_eI[eoff+2*p+1]*64 + hw];
            float2 b1 = ((const float2*)g_preB)[s_eJ[eoff+2*p+1]*64 + hw];
            gA[p] = pack2(a0.x + b0.x + cv.x, a1.x + b1.x + cv.x);
            gB[p] = pack2(a0.y + b0.y + cv.y, a1.y + b1.y + cv.y);
        }

        #pragma unroll 4
        for (int k = 0; k < 256; k++) {
            float2 w = __ldg(&Wc2[k*64 + hw]);
            ull wa = pack2(w.x, w.x);
            ull wb = pack2(w.y, w.y);
            const ulonglong2 s01 = *(const ulonglong2*)&sh[k*SHS + eoff];
            const ulonglong2 s23 = *(const ulonglong2*)&sh[k*SHS + eoff + 4];
            gA[0] = fma2(s01.x, wa, gA[0]);
            gA[1] = fma2(s01.y, wa, gA[1]);
            gA[2] = fma2(s23.x, wa, gA[2]);
            gA[3] = fma2(s23.y, wa, gA[3]);
            gB[0] = fma2(s01.x, wb, gB[0]);
            gB[1] = fma2(s01.y, wb, gB[1]);
            gB[2] = fma2(s23.x, wb, gB[2]);
            gB[3] = fma2(s23.y, wb, gB[3]);
        }

        // silu + run-compressed atomic aggregation
        int neH = ne - eoff; neH = neH < 0 ? 0 : (neH > 8 ? 8 : neH);
        float mA[8], mB[8];
        #pragma unroll
        for (int p = 0; p < 4; p++) {
            float lo, hi;
            unpack2(gA[p], lo, hi); mA[2*p] = silu_f(lo); mA[2*p+1] = silu_f(hi);
            unpack2(gB[p], lo, hi); mB[2*p] = silu_f(lo); mB[2*p+1] = silu_f(hi);
        }
        int cur = -1; float sA = 0.f, sB = 0.f;
        int hh = 2*hw;
        #pragma unroll
        for (int e = 0; e < 8; e++) {
            if (e < neH) {
                int i = s_eI[eoff + e];
                if (i != cur) {
                    if (cur >= 0) {
                        atomicAdd(&g_agg[cur*Hh + hh],     sA);
                        atomicAdd(&g_agg[cur*Hh + hh + 1], sB);
                    }
                    cur = i; sA = mA[e]; sB = mB[e];
                } else { sA += mA[e]; sB += mB[e]; }
            }
        }
        if (cur >= 0) {
            atomicAdd(&g_agg[cur*Hh + hh],     sA);
            atomicAdd(&g_agg[cur*Hh + hh + 1], sB);
        }
    }
}

// node update (+ next-block preA/preB, or output head on last block)
__global__ void k_node(const float* __restrict__ ew2, const float* __restrict__ eb2,
                       const float* __restrict__ nw1, const float* __restrict__ nb1,
                       const float* __restrict__ nw2, const float* __restrict__ nb2,
                       const float* __restrict__ ew1,
                       const float* __restrict__ ow1, const float* __restrict__ ob1,
                       const float* __restrict__ ow2, const float* __restrict__ ob2,
                       const float* __restrict__ mask, float* __restrict__ out, int t) {
    int row = blockIdx.x, h = threadIdx.x;
    __shared__ float x[256];
    __shared__ float agg_s[Hh];
    __shared__ float u[Hh];
    __shared__ float red[4];
    float fh = g_F[row*Hh + h];
    x[h] = fh;
    agg_s[h] = g_agg[row*Hh + h];
    __syncthreads();
    const float* EW2 = ew2 + (size_t)t*Hh*Hh;
    float deg = (float)g_cnt[row];
    float s = deg * eb2[t*Hh + h];
    #pragma unroll 4
    for (int k = 0; k < Hh; k++) s += agg_s[k] * EW2[k*Hh + h];
    x[128 + h] = s;
    __syncthreads();
    const float* NW1 = nw1 + (size_t)t*256*Hh;
    float uacc = nb1[t*Hh + h];
    #pragma unroll 4
    for (int k = 0; k < 256; k++) uacc += x[k] * NW1[k*Hh + h];
    u[h] = silu_f(uacc);
    __syncthreads();
    const float* NW2 = nw2 + (size_t)t*Hh*Hh;
    float upd = nb2[t*Hh + h];
    #pragma unroll 4
    for (int k = 0; k < Hh; k++) upd += u[k] * NW2[k*Hh + h];
    float newf = fh + upd;
    g_F[row*Hh + h] = newf;

    if (t + 1 < NBt) {
        x[h] = newf;
        __syncthreads();
        const float* W1a = ew1 + (size_t)(t+1)*4*Hh*Hh;
        const float* W1b = W1a + Hh*Hh;
        float a = 0.f, bv = 0.f;
        #pragma unroll 4
        for (int k = 0; k < Hh; k++) {
            float fk = x[k];
            a  += fk * W1a[k*Hh + h];
            bv += fk * W1b[k*Hh + h];
        }
        g_preA[row*Hh + h] = a;
        g_preB[row*Hh + h] = bv;
        g_agg[row*Hh + h] = 0.f;
    } else {
        // output head
        x[h] = newf;
        __syncthreads();
        float oacc = ob1[h];
        #pragma unroll 4
        for (int k = 0; k < Hh; k++) oacc += x[k] * ow1[k*Hh + h];
        float val = silu_f(oacc) * ow2[h];
        #pragma unroll
        for (int off = 16; off > 0; off >>= 1)
            val += __shfl_down_sync(0xffffffffu, val, off);
        if ((h & 31) == 0) red[h >> 5] = val;
        __syncthreads();
        if (h == 0) {
            float v = red[0] + red[1] + red[2] + red[3] + ob2[0];
            v *= mask[row];
            atomicAdd(&out[row / Nn], v);
        }
    }
}

extern "C" void kernel_launch(void* const* d_in, const int* in_sizes, int n_in,
                              void* d_out, int out_size) {
    const int*   node_indices = (const int*)  d_in[0];
    const float* positions    = (const float*)d_in[1];
    const int*   adjacency    = (const int*)  d_in[2];
    const float* mask         = (const float*)d_in[3];
    const float* emb          = (const float*)d_in[4];
    const float* dpw          = (const float*)d_in[5];
    const float* dpb          = (const float*)d_in[6];
    const float* rbf_w1 = (const float*)d_in[7];
    const float* rbf_b1 = (const float*)d_in[8];
    const float* rbf_w2 = (const float*)d_in[9];
    const float* rbf_b2 = (const float*)d_in[10];
    const float* dir_w1 = (const float*)d_in[11];
    const float* dir_b1 = (const float*)d_in[12];
    const float* dir_w2 = (const float*)d_in[13];
    const float* dir_b2 = (const float*)d_in[14];
    const float* edge_w1 = (const float*)d_in[15];
    const float* edge_b1 = (const float*)d_in[16];
    const float* edge_w2 = (const float*)d_in[17];
    const float* edge_b2 = (const float*)d_in[18];
    const float* node_w1 = (const float*)d_in[19];
    const float* node_b1 = (const float*)d_in[20];
    const float* node_w2 = (const float*)d_in[21];
    const float* node_b2 = (const float*)d_in[22];
    const float* ow1 = (const float*)d_in[23];
    const float* ob1 = (const float*)d_in[24];
    const float* ow2 = (const float*)d_in[25];
    const float* ob2 = (const float*)d_in[26];
    float* out = (float*)d_out;

    k_init<<<ROWS, Hh>>>(node_indices, emb, edge_w1, out);
    k_edges<<<ROWS, Nn>>>(positions, adjacency, mask, dpw, dpb);
    k_fold<<<3*257, Hh>>>(rbf_w2, rbf_b2, dir_w2, dir_b2, edge_w1, edge_b1);
    for (int t = 0; t < NBt; t++) {
        k_edge_mlp<<<GRID_E, Hh>>>(rbf_w1, rbf_b1, dir_w1, dir_b1, t);
        k_node<<<ROWS, Hh>>>(edge_w2, edge_b2, node_w1, node_b1, node_w2, node_b2,
                             edge_w1, ow1, ob1, ow2, ob2, mask, out, t);
    }
}